// round 1
// baseline (speedup 1.0000x reference)
#include <cuda_runtime.h>
#include <cstdint>
#include <math.h>

#define TOKENS 16384
#define DIM    2048
#define NEXP   8
#define RANK   16
#define NFEAT  128         // NEXP*RANK
#define KC     32          // K chunk for GEMM1
#define NIT    (DIM/KC)    // 64
#define PAD1   36          // KC padded (conflict-free: 36%32==4, 16B-aligned rows)
#define PAD2   132         // NFEAT padded (132%32==4, 528B rows, 16B-aligned)
#define SA_STAGE (128*PAD1)  // floats per stage per operand

// -------- device scratch (no allocations allowed) --------
__device__ float g_mask[TOKENS*NEXP];
__device__ float g_B2[DIM*NFEAT];          // B2[d][j] = Bm[e][d][r], j=e*16+r
__device__ float g_probs_fallback[TOKENS*NEXP];

// -------- helpers --------
__device__ __forceinline__ uint32_t f2tf(float f){
    uint32_t u; asm("cvt.rna.tf32.f32 %0, %1;" : "=r"(u) : "f"(f)); return u;
}
__device__ __forceinline__ void mma8(float c[4], const uint32_t a[4], const uint32_t b[2]){
    asm volatile(
      "mma.sync.aligned.m16n8k8.row.col.f32.tf32.tf32.f32 "
      "{%0,%1,%2,%3},{%4,%5,%6,%7},{%8,%9},{%0,%1,%2,%3};"
      : "+f"(c[0]), "+f"(c[1]), "+f"(c[2]), "+f"(c[3])
      : "r"(a[0]), "r"(a[1]), "r"(a[2]), "r"(a[3]), "r"(b[0]), "r"(b[1]));
}
__device__ __forceinline__ void cp16(void* s, const void* g){
    uint32_t sa = (uint32_t)__cvta_generic_to_shared(s);
    asm volatile("cp.async.cg.shared.global [%0], [%1], 16;" :: "r"(sa), "l"(g));
}
__device__ __forceinline__ void cp_commit(){ asm volatile("cp.async.commit_group;"); }
template<int N> __device__ __forceinline__ void cp_wait(){
    asm volatile("cp.async.wait_group %0;" :: "n"(N));
}
__device__ __forceinline__ float gelu_exact(float v){
    return 0.5f * v * (1.0f + erff(v * 0.70710678118654752f));
}

// ======================= Kernel 1: gate (fp32 exact) =======================
// block = 256 thr = 8 warps, each warp handles 4 tokens. grid = 512.
__global__ __launch_bounds__(256) void gate_kernel(
    const float* __restrict__ x, const float* __restrict__ W,
    const float* __restrict__ bias, float* __restrict__ probs)
{
    int warp = threadIdx.x >> 5, lane = threadIdx.x & 31;
    int tok0 = (blockIdx.x * 8 + warp) * 4;
    const float4* x4 = reinterpret_cast<const float4*>(x);
    const float4* W4 = reinterpret_cast<const float4*>(W);

    float acc[4][8];
    #pragma unroll
    for (int t = 0; t < 4; t++)
        #pragma unroll
        for (int e = 0; e < 8; e++) acc[t][e] = 0.f;

    for (int i = lane; i < 512; i += 32){
        float4 xv[4];
        #pragma unroll
        for (int t = 0; t < 4; t++) xv[t] = x4[(size_t)(tok0 + t) * 512 + i];
        #pragma unroll
        for (int e = 0; e < 8; e++){
            float4 w = W4[e * 512 + i];
            #pragma unroll
            for (int t = 0; t < 4; t++)
                acc[t][e] += xv[t].x*w.x + xv[t].y*w.y + xv[t].z*w.z + xv[t].w*w.w;
        }
    }
    #pragma unroll
    for (int t = 0; t < 4; t++)
        #pragma unroll
        for (int e = 0; e < 8; e++){
            float v = acc[t][e];
            #pragma unroll
            for (int s = 16; s > 0; s >>= 1) v += __shfl_xor_sync(0xffffffffu, v, s);
            acc[t][e] = v;
        }
    #pragma unroll
    for (int t = 0; t < 4; t++){
        if (lane == t){
            int tok = tok0 + t;
            float lg[8]; float mx = -1e30f;
            #pragma unroll
            for (int e = 0; e < 8; e++){ lg[e] = acc[t][e] + bias[e]; mx = fmaxf(mx, lg[e]); }
            float p[8]; float s = 0.f;
            #pragma unroll
            for (int e = 0; e < 8; e++){ p[e] = expf(lg[e] - mx); s += p[e]; }
            float inv = 1.f / s;
            #pragma unroll
            for (int e = 0; e < 8; e++) probs[tok*8 + e] = p[e] * inv;
            // top-2 (stable: lowest index wins ties, matching jax top_k)
            int i1 = 0;
            #pragma unroll
            for (int e = 1; e < 8; e++) if (lg[e] > lg[i1]) i1 = e;
            int i2 = (i1 == 0) ? 1 : 0;
            #pragma unroll
            for (int e = 0; e < 8; e++) if (e != i1 && lg[e] > lg[i2]) i2 = e;
            #pragma unroll
            for (int e = 0; e < 8; e++)
                g_mask[tok*8 + e] = (e == i1 || e == i2) ? 1.0f : 0.0f;
        }
    }
}

// ======================= Kernel 2: pack Bm -> B2[d][j] =======================
__global__ void pack_kernel(const float* __restrict__ Bm){
    int t = blockIdx.x * blockDim.x + threadIdx.x;
    if (t < DIM * NFEAT){
        int d = t >> 7; int j = t & 127; int e = j >> 4; int r = j & 15;
        g_B2[t] = Bm[e * (DIM * RANK) + d * RANK + r];
    }
}

// ================= Kernel 3: fused GEMM1 -> gelu*mask -> GEMM2 =================
// tile = 128 tokens. grid = 128 CTAs, 256 threads (4 M-warps x 2 N-warps).
__global__ __launch_bounds__(256) void fused_kernel(
    const float* __restrict__ x, const float* __restrict__ W1,
    float* __restrict__ out)
{
    extern __shared__ float sm[];
    float* As  = sm;                       // 2 stages * 4608
    float* Ws  = As + 2 * SA_STAGE;        // 2 stages * 4608
    float* Hs  = Ws + 2 * SA_STAGE;        // 128*PAD2
    float* Bs2 = Hs + 128 * PAD2;          // 128*PAD2
    float* msk = Bs2 + 128 * PAD2;         // 128*8

    const int tid  = threadIdx.x;
    const int warp = tid >> 5, lane = tid & 31;
    const int g = lane >> 2, t4 = lane & 3;
    const int mw = warp & 3, nw = warp >> 2;
    const int tokBase = blockIdx.x * 128;

    // stage top-2 mask for this token tile
    #pragma unroll
    for (int i = 0; i < 4; i++)
        msk[tid + i*256] = g_mask[tokBase*8 + tid + i*256];

    // ---------------- GEMM1: H = X @ W1^T (tf32), K = 2048 ----------------
    float acc[2][8][4];
    #pragma unroll
    for (int mf = 0; mf < 2; mf++)
        #pragma unroll
        for (int nf = 0; nf < 8; nf++)
            #pragma unroll
            for (int k = 0; k < 4; k++) acc[mf][nf][k] = 0.f;

    auto copyAW = [&](int st, int it){
        int kb = it * KC;
        #pragma unroll
        for (int i = 0; i < 4; i++){
            int q = tid + i*256; int row = q >> 3; int c4 = q & 7;
            cp16(&As[st*SA_STAGE + row*PAD1 + c4*4],
                 &x[(size_t)(tokBase + row) * DIM + kb + c4*4]);
            cp16(&Ws[st*SA_STAGE + row*PAD1 + c4*4],
                 &W1[(size_t)row * DIM + kb + c4*4]);
        }
    };

    copyAW(0, 0); cp_commit();

    for (int it = 0; it < NIT; ++it){
        int st = it & 1;
        if (it + 1 < NIT){ copyAW(st ^ 1, it + 1); cp_commit(); cp_wait<1>(); }
        else             { cp_wait<0>(); }
        __syncthreads();

        const float* Ab = As + st*SA_STAGE + mw*32*PAD1;
        const float* Wb = Ws + st*SA_STAGE + nw*64*PAD1;
        #pragma unroll
        for (int ks = 0; ks < 4; ks++){
            int kc = ks * 8;
            uint32_t a[2][4];
            #pragma unroll
            for (int mf = 0; mf < 2; mf++){
                a[mf][0] = f2tf(Ab[(mf*16 +     g)*PAD1 + kc + t4]);
                a[mf][1] = f2tf(Ab[(mf*16 + 8 + g)*PAD1 + kc + t4]);
                a[mf][2] = f2tf(Ab[(mf*16 +     g)*PAD1 + kc + t4 + 4]);
                a[mf][3] = f2tf(Ab[(mf*16 + 8 + g)*PAD1 + kc + t4 + 4]);
            }
            #pragma unroll
            for (int nf = 0; nf < 8; nf++){
                uint32_t b[2];
                b[0] = f2tf(Wb[(nf*8 + g)*PAD1 + kc + t4]);
                b[1] = f2tf(Wb[(nf*8 + g)*PAD1 + kc + t4 + 4]);
                #pragma unroll
                for (int mf = 0; mf < 2; mf++) mma8(acc[mf][nf], a[mf], b);
            }
        }
        __syncthreads();
    }

    // --------- epilogue 1: H' = gelu(H) * mask  (stored to SMEM only) ---------
    #pragma unroll
    for (int mf = 0; mf < 2; mf++){
        int r0 = mw*32 + mf*16 + g;
        #pragma unroll
        for (int nf = 0; nf < 8; nf++){
            int c0 = nw*64 + nf*8 + t4*2;
            int ex = c0 >> 4;
            float m0 = msk[r0*8 + ex];
            float m1 = msk[(r0+8)*8 + ex];
            Hs[r0*PAD2 + c0]       = gelu_exact(acc[mf][nf][0]) * m0;
            Hs[r0*PAD2 + c0 + 1]   = gelu_exact(acc[mf][nf][1]) * m0;
            Hs[(r0+8)*PAD2 + c0]   = gelu_exact(acc[mf][nf][2]) * m1;
            Hs[(r0+8)*PAD2 + c0+1] = gelu_exact(acc[mf][nf][3]) * m1;
        }
    }
    __syncthreads();

    // ---------------- GEMM2: out = H' @ B2^T (tf32), K = 128 ----------------
    for (int n2 = 0; n2 < 16; n2++){
        int dBase = n2 * 128;
        #pragma unroll
        for (int i = 0; i < 16; i++){
            int q = tid + i*256; int row = q >> 5; int c4 = q & 31;
            cp16(&Bs2[row*PAD2 + c4*4], &g_B2[(size_t)(dBase + row)*NFEAT + c4*4]);
        }
        cp_commit(); cp_wait<0>();
        __syncthreads();

        float acc2[2][8][4];
        #pragma unroll
        for (int mf = 0; mf < 2; mf++)
            #pragma unroll
            for (int nf = 0; nf < 8; nf++)
                #pragma unroll
                for (int k = 0; k < 4; k++) acc2[mf][nf][k] = 0.f;

        const float* Hb = Hs  + mw*32*PAD2;
        const float* Bb = Bs2 + nw*64*PAD2;
        #pragma unroll 4
        for (int ks = 0; ks < 16; ks++){
            int kc = ks * 8;
            uint32_t a[2][4];
            #pragma unroll
            for (int mf = 0; mf < 2; mf++){
                a[mf][0] = f2tf(Hb[(mf*16 +     g)*PAD2 + kc + t4]);
                a[mf][1] = f2tf(Hb[(mf*16 + 8 + g)*PAD2 + kc + t4]);
                a[mf][2] = f2tf(Hb[(mf*16 +     g)*PAD2 + kc + t4 + 4]);
                a[mf][3] = f2tf(Hb[(mf*16 + 8 + g)*PAD2 + kc + t4 + 4]);
            }
            #pragma unroll
            for (int nf = 0; nf < 8; nf++){
                uint32_t b[2];
                b[0] = f2tf(Bb[(nf*8 + g)*PAD2 + kc + t4]);
                b[1] = f2tf(Bb[(nf*8 + g)*PAD2 + kc + t4 + 4]);
                #pragma unroll
                for (int mf = 0; mf < 2; mf++) mma8(acc2[mf][nf], a[mf], b);
            }
        }

        // store out tile (coalesced float2)
        #pragma unroll
        for (int mf = 0; mf < 2; mf++){
            int r0 = tokBase + mw*32 + mf*16 + g;
            #pragma unroll
            for (int nf = 0; nf < 8; nf++){
                int c0 = dBase + nw*64 + nf*8 + t4*2;
                *reinterpret_cast<float2*>(&out[(size_t)r0*DIM + c0]) =
                    make_float2(acc2[mf][nf][0], acc2[mf][nf][1]);
                *reinterpret_cast<float2*>(&out[(size_t)(r0+8)*DIM + c0]) =
                    make_float2(acc2[mf][nf][2], acc2[mf][nf][3]);
            }
        }
        __syncthreads();
    }
}

// ============================ launch ============================
extern "C" void kernel_launch(void* const* d_in, const int* in_sizes, int n_in,
                              void* d_out, int out_size)
{
    const float* x  = (const float*)d_in[0];
    const float* gW = (const float*)d_in[1];
    const float* gb = (const float*)d_in[2];
    const float* A  = (const float*)d_in[3];   // [8,16,2048] == W1 [128,2048]
    const float* Bm = (const float*)d_in[4];   // [8,2048,16]

    float* out = (float*)d_out;
    float* probs = out + (size_t)TOKENS * DIM;
    if (out_size < TOKENS*DIM + TOKENS*NEXP){
        void* p = nullptr;
        cudaGetSymbolAddress(&p, g_probs_fallback);
        probs = (float*)p;
    }

    gate_kernel<<<512, 256>>>(x, gW, gb, probs);
    pack_kernel<<<512, 512>>>(Bm);

    size_t smem_bytes = (size_t)(4*SA_STAGE + 2*128*PAD2 + 128*NEXP) * sizeof(float);
    cudaFuncSetAttribute(fused_kernel, cudaFuncAttributeMaxDynamicSharedMemorySize,
                         (int)smem_bytes);
    fused_kernel<<<128, 256, smem_bytes>>>(x, A, out);
}

// round 2
// speedup vs baseline: 1.1476x; 1.1476x over previous
#include <cuda_runtime.h>
#include <cstdint>
#include <math.h>

#define TOKENS 16384
#define DIM    2048
#define NEXP   8
#define RANK   16
#define NFEAT  128
#define KC     32
#define NIT    (DIM/KC)      // 64
#define PAD1   36            // 36%32==4 -> conflict-free, 16B-aligned rows
#define PAD2   132           // 132%32==4
#define SA_STAGE (128*PAD1)

// -------- device scratch --------
__device__ float g_mask[TOKENS*NEXP];
__device__ float g_B2[DIM*NFEAT];     // pre-rounded tf32 bits: B2[d][j]=Bm[e][d][r]
__device__ float g_W1c[NFEAT*DIM];    // pre-rounded tf32 bits of A ([128,2048])
__device__ float g_probs_fallback[TOKENS*NEXP];

// -------- helpers --------
__device__ __forceinline__ uint32_t f2tf(float f){
    uint32_t u; asm("cvt.rna.tf32.f32 %0, %1;" : "=r"(u) : "f"(f)); return u;
}
__device__ __forceinline__ float rndtf(float f){ return __uint_as_float(f2tf(f)); }
__device__ __forceinline__ void mma8(float c[4], const uint32_t a[4], const uint32_t b[2]){
    asm volatile(
      "mma.sync.aligned.m16n8k8.row.col.f32.tf32.tf32.f32 "
      "{%0,%1,%2,%3},{%4,%5,%6,%7},{%8,%9},{%0,%1,%2,%3};"
      : "+f"(c[0]), "+f"(c[1]), "+f"(c[2]), "+f"(c[3])
      : "r"(a[0]), "r"(a[1]), "r"(a[2]), "r"(a[3]), "r"(b[0]), "r"(b[1]));
}
__device__ __forceinline__ void cp16(void* s, const void* g){
    uint32_t sa = (uint32_t)__cvta_generic_to_shared(s);
    asm volatile("cp.async.cg.shared.global [%0], [%1], 16;" :: "r"(sa), "l"(g));
}
__device__ __forceinline__ void cp_commit(){ asm volatile("cp.async.commit_group;"); }
template<int N> __device__ __forceinline__ void cp_wait(){
    asm volatile("cp.async.wait_group %0;" :: "n"(N));
}
__device__ __forceinline__ float gelu_exact(float v){
    return 0.5f * v * (1.0f + erff(v * 0.70710678118654752f));
}

// ================= Kernel 1: gate (fp32 exact), high occupancy =================
// 512 thr = 16 warps, 2 tokens/warp -> 32 tokens/CTA, grid 512. W staged in SMEM.
__global__ __launch_bounds__(512) void gate_kernel(
    const float* __restrict__ x, const float* __restrict__ W,
    const float* __restrict__ bias, float* __restrict__ probs)
{
    extern __shared__ float Wsm[];           // 8*2048 floats = 64KB
    {
        const float4* Wg = reinterpret_cast<const float4*>(W);
        float4* Ws4 = reinterpret_cast<float4*>(Wsm);
        #pragma unroll
        for (int i = threadIdx.x; i < NEXP*DIM/4; i += 512) Ws4[i] = Wg[i];
    }
    __syncthreads();

    int warp = threadIdx.x >> 5, lane = threadIdx.x & 31;
    int tok0 = (blockIdx.x * 16 + warp) * 2;
    const float4* x4 = reinterpret_cast<const float4*>(x);
    const float4* W4 = reinterpret_cast<const float4*>(Wsm);

    float acc[2][8];
    #pragma unroll
    for (int t = 0; t < 2; t++)
        #pragma unroll
        for (int e = 0; e < 8; e++) acc[t][e] = 0.f;

    #pragma unroll 4
    for (int i = lane; i < 512; i += 32){
        float4 xv0 = x4[(size_t)tok0 * 512 + i];
        float4 xv1 = x4[(size_t)(tok0 + 1) * 512 + i];
        #pragma unroll
        for (int e = 0; e < 8; e++){
            float4 w = W4[e * 512 + i];
            acc[0][e] += xv0.x*w.x + xv0.y*w.y + xv0.z*w.z + xv0.w*w.w;
            acc[1][e] += xv1.x*w.x + xv1.y*w.y + xv1.z*w.z + xv1.w*w.w;
        }
    }
    #pragma unroll
    for (int t = 0; t < 2; t++)
        #pragma unroll
        for (int e = 0; e < 8; e++){
            float v = acc[t][e];
            #pragma unroll
            for (int s = 16; s > 0; s >>= 1) v += __shfl_xor_sync(0xffffffffu, v, s);
            acc[t][e] = v;
        }
    if (lane < 2){
        int t = lane;
        int tok = tok0 + t;
        float lg[8]; float mx = -1e30f;
        #pragma unroll
        for (int e = 0; e < 8; e++){ lg[e] = acc[t][e] + bias[e]; mx = fmaxf(mx, lg[e]); }
        float p[8]; float s = 0.f;
        #pragma unroll
        for (int e = 0; e < 8; e++){ p[e] = expf(lg[e] - mx); s += p[e]; }
        float inv = 1.f / s;
        #pragma unroll
        for (int e = 0; e < 8; e++) probs[tok*8 + e] = p[e] * inv;
        // top-2 (lowest index wins ties, matching jax top_k)
        int i1 = 0;
        #pragma unroll
        for (int e = 1; e < 8; e++) if (lg[e] > lg[i1]) i1 = e;
        int i2 = (i1 == 0) ? 1 : 0;
        #pragma unroll
        for (int e = 0; e < 8; e++) if (e != i1 && lg[e] > lg[i2]) i2 = e;
        #pragma unroll
        for (int e = 0; e < 8; e++)
            g_mask[tok*8 + e] = (e == i1 || e == i2) ? 1.0f : 0.0f;
    }
}

// ========== Kernel 2: pack + pre-round weights to tf32 bit patterns ==========
__global__ void pack_kernel(const float* __restrict__ Bm, const float* __restrict__ A){
    int t = blockIdx.x * blockDim.x + threadIdx.x;
    if (t < DIM * NFEAT){
        int d = t >> 7; int j = t & 127; int e = j >> 4; int r = j & 15;
        g_B2[t] = rndtf(Bm[e * (DIM * RANK) + d * RANK + r]);
    } else {
        int u = t - DIM * NFEAT;
        if (u < NFEAT * DIM) g_W1c[u] = rndtf(A[u]);
    }
}

// ========= Kernel 3: fused GEMM1 -> gelu*mask -> GEMM2, 512 threads =========
// 128 tokens/CTA, grid 128. 16 warps in 4x4 grid. Warp tiles: 32x32 (G1), 32x16 (G2).
__global__ __launch_bounds__(512) void fused_kernel(
    const float* __restrict__ x, float* __restrict__ out)
{
    extern __shared__ float sm[];
    float* As  = sm;                        // 2 * 4608
    float* Ws  = As + 2 * SA_STAGE;         // 2 * 4608
    float* Hs  = Ws + 2 * SA_STAGE;         // 128*132
    float* Bs2 = Hs + 128 * PAD2;           // 2 * 64*132
    float* msk = Bs2 + 2 * 64 * PAD2;       // 128*8

    const int tid  = threadIdx.x;
    const int warp = tid >> 5, lane = tid & 31;
    const int g = lane >> 2, t4 = lane & 3;
    const int mw = warp & 3, nw = warp >> 2;
    const int tokBase = blockIdx.x * 128;

    // stage top-2 mask
    #pragma unroll
    for (int i = 0; i < 2; i++)
        msk[tid + i*512] = g_mask[tokBase*8 + tid + i*512];

    // ---------------- GEMM1: H = X @ W1^T (tf32), K = 2048 ----------------
    float acc[2][4][4];
    #pragma unroll
    for (int mf = 0; mf < 2; mf++)
        #pragma unroll
        for (int nf = 0; nf < 4; nf++)
            #pragma unroll
            for (int k = 0; k < 4; k++) acc[mf][nf][k] = 0.f;

    auto copyAW = [&](int st, int it){
        int kb = it * KC;
        #pragma unroll
        for (int i = 0; i < 2; i++){
            int q = tid + i*512; int row = q >> 3; int c4 = q & 7;
            cp16(&As[st*SA_STAGE + row*PAD1 + c4*4],
                 &x[(size_t)(tokBase + row) * DIM + kb + c4*4]);
        }
        #pragma unroll
        for (int i = 0; i < 2; i++){
            int q = tid + i*512; int row = q >> 3; int c4 = q & 7;
            cp16(&Ws[st*SA_STAGE + row*PAD1 + c4*4],
                 &g_W1c[(size_t)row * DIM + kb + c4*4]);
        }
    };

    copyAW(0, 0); cp_commit();

    for (int it = 0; it < NIT; ++it){
        int st = it & 1;
        if (it + 1 < NIT){ copyAW(st ^ 1, it + 1); cp_commit(); cp_wait<1>(); }
        else             { cp_wait<0>(); }
        __syncthreads();

        const float* Ab = As + st*SA_STAGE + mw*32*PAD1;
        const float* Wb = Ws + st*SA_STAGE + nw*32*PAD1;
        #pragma unroll
        for (int ks = 0; ks < 4; ks++){
            int kc = ks * 8;
            uint32_t a[2][4];
            #pragma unroll
            for (int mf = 0; mf < 2; mf++){
                a[mf][0] = f2tf(Ab[(mf*16 +     g)*PAD1 + kc + t4]);
                a[mf][1] = f2tf(Ab[(mf*16 + 8 + g)*PAD1 + kc + t4]);
                a[mf][2] = f2tf(Ab[(mf*16 +     g)*PAD1 + kc + t4 + 4]);
                a[mf][3] = f2tf(Ab[(mf*16 + 8 + g)*PAD1 + kc + t4 + 4]);
            }
            #pragma unroll
            for (int nf = 0; nf < 4; nf++){
                uint32_t b[2];   // pre-rounded: raw bit loads, no cvt
                b[0] = __float_as_uint(Wb[(nf*8 + g)*PAD1 + kc + t4]);
                b[1] = __float_as_uint(Wb[(nf*8 + g)*PAD1 + kc + t4 + 4]);
                #pragma unroll
                for (int mf = 0; mf < 2; mf++) mma8(acc[mf][nf], a[mf], b);
            }
        }
        __syncthreads();
    }

    // ------ epilogue 1: H' = round_tf32(gelu(H) * mask) stored to SMEM ------
    #pragma unroll
    for (int mf = 0; mf < 2; mf++){
        int r0 = mw*32 + mf*16 + g;
        #pragma unroll
        for (int nf = 0; nf < 4; nf++){
            int c0 = nw*32 + nf*8 + t4*2;
            int ex = c0 >> 4;
            float m0 = msk[r0*8 + ex];
            float m1 = msk[(r0+8)*8 + ex];
            Hs[r0*PAD2 + c0]       = rndtf(gelu_exact(acc[mf][nf][0]) * m0);
            Hs[r0*PAD2 + c0 + 1]   = rndtf(gelu_exact(acc[mf][nf][1]) * m0);
            Hs[(r0+8)*PAD2 + c0]   = rndtf(gelu_exact(acc[mf][nf][2]) * m1);
            Hs[(r0+8)*PAD2 + c0+1] = rndtf(gelu_exact(acc[mf][nf][3]) * m1);
        }
    }

    // ------------- GEMM2: out = H' @ B2^T, K = 128, 32 chunks of 64 dims -------------
    auto loadB = [&](int buf, int n2){
        int dBase = n2 * 64;
        #pragma unroll
        for (int i = 0; i < 4; i++){
            int q = tid + i*512; int row = q >> 5; int c4 = q & 31;
            cp16(&Bs2[buf*64*PAD2 + row*PAD2 + c4*4],
                 &g_B2[(size_t)(dBase + row)*NFEAT + c4*4]);
        }
    };

    loadB(0, 0); cp_commit();

    for (int n2 = 0; n2 < 32; n2++){
        int b = n2 & 1;
        if (n2 + 1 < 32){ loadB(b ^ 1, n2 + 1); cp_commit(); cp_wait<1>(); }
        else            { cp_wait<0>(); }
        __syncthreads();

        float acc2[2][2][4];
        #pragma unroll
        for (int mf = 0; mf < 2; mf++)
            #pragma unroll
            for (int nf = 0; nf < 2; nf++)
                #pragma unroll
                for (int k = 0; k < 4; k++) acc2[mf][nf][k] = 0.f;

        const float* Hb = Hs + mw*32*PAD2;
        const float* Bb = Bs2 + b*64*PAD2 + nw*16*PAD2;
        #pragma unroll
        for (int ks = 0; ks < 16; ks++){
            int kc = ks * 8;
            uint32_t a[2][4];   // H' pre-rounded: raw loads
            #pragma unroll
            for (int mf = 0; mf < 2; mf++){
                a[mf][0] = __float_as_uint(Hb[(mf*16 +     g)*PAD2 + kc + t4]);
                a[mf][1] = __float_as_uint(Hb[(mf*16 + 8 + g)*PAD2 + kc + t4]);
                a[mf][2] = __float_as_uint(Hb[(mf*16 +     g)*PAD2 + kc + t4 + 4]);
                a[mf][3] = __float_as_uint(Hb[(mf*16 + 8 + g)*PAD2 + kc + t4 + 4]);
            }
            #pragma unroll
            for (int nf = 0; nf < 2; nf++){
                uint32_t bfr[2];
                bfr[0] = __float_as_uint(Bb[(nf*8 + g)*PAD2 + kc + t4]);
                bfr[1] = __float_as_uint(Bb[(nf*8 + g)*PAD2 + kc + t4 + 4]);
                #pragma unroll
                for (int mf = 0; mf < 2; mf++) mma8(acc2[mf][nf], a[mf], bfr);
            }
        }

        int dBase = n2 * 64;
        #pragma unroll
        for (int mf = 0; mf < 2; mf++){
            int r0 = tokBase + mw*32 + mf*16 + g;
            #pragma unroll
            for (int nf = 0; nf < 2; nf++){
                int c0 = dBase + nw*16 + nf*8 + t4*2;
                *reinterpret_cast<float2*>(&out[(size_t)r0*DIM + c0]) =
                    make_float2(acc2[mf][nf][0], acc2[mf][nf][1]);
                *reinterpret_cast<float2*>(&out[(size_t)(r0+8)*DIM + c0]) =
                    make_float2(acc2[mf][nf][2], acc2[mf][nf][3]);
            }
        }
        __syncthreads();
    }
}

// ============================ launch ============================
extern "C" void kernel_launch(void* const* d_in, const int* in_sizes, int n_in,
                              void* d_out, int out_size)
{
    const float* x  = (const float*)d_in[0];
    const float* gW = (const float*)d_in[1];
    const float* gb = (const float*)d_in[2];
    const float* A  = (const float*)d_in[3];   // [8,16,2048] == W1 [128,2048]
    const float* Bm = (const float*)d_in[4];   // [8,2048,16]

    float* out = (float*)d_out;
    float* probs = out + (size_t)TOKENS * DIM;
    if (out_size < TOKENS*DIM + TOKENS*NEXP){
        void* p = nullptr;
        cudaGetSymbolAddress(&p, g_probs_fallback);
        probs = (float*)p;
    }

    size_t gate_smem = (size_t)NEXP * DIM * sizeof(float);   // 64KB
    static int s_init = 0;
    if (!s_init){
        cudaFuncSetAttribute(gate_kernel, cudaFuncAttributeMaxDynamicSharedMemorySize,
                             (int)gate_smem);
        size_t fused_smem = (size_t)(4*SA_STAGE + 128*PAD2 + 2*64*PAD2 + 128*NEXP)
                            * sizeof(float);
        cudaFuncSetAttribute(fused_kernel, cudaFuncAttributeMaxDynamicSharedMemorySize,
                             (int)fused_smem);
        s_init = 1;
    }

    gate_kernel<<<512, 512, gate_smem>>>(x, gW, gb, probs);
    pack_kernel<<<(2*DIM*NFEAT + 511)/512, 512>>>(Bm, A);

    size_t fused_smem = (size_t)(4*SA_STAGE + 128*PAD2 + 2*64*PAD2 + 128*NEXP)
                        * sizeof(float);
    fused_kernel<<<128, 512, fused_smem>>>(x, out);
}